// round 4
// baseline (speedup 1.0000x reference)
#include <cuda_runtime.h>

// Fused gate table: [channel][pair k][u00r,u00i,u01r,u01i,u10r,u10i,u11r,u11i]
// U = Rx(tx) * Rz(tz) acting on the ctrl=1 subspace.
__device__ float g_U[4][8][8];
// Per-pixel trig of the channel-averaged image: (sin(pi*p), -cos(pi*p))
__device__ float2 g_pix[8 * 30 * 30];

__global__ void quanv_prep_kernel(const float* __restrict__ x,
                                  const float* __restrict__ qp) {
    int t = blockIdx.x * blockDim.x + threadIdx.x;
    if (t < 7200) {
        const float* px = x + t * 3;
        float p = (px[0] + px[1] + px[2]) * (1.0f / 3.0f);
        float sp, cp;
        sincospif(p, &sp, &cp);
        g_pix[t] = make_float2(sp, -cp);   // (cq, sq) of the RX half-angle
    } else if (t < 7232) {
        int u = t - 7200;
        int ch = u >> 3, k = u & 7;
        float tz = qp[ch * 16 + 2 * k];
        float tx = qp[ch * 16 + 2 * k + 1];
        float ca = cosf(0.5f * tz), sa = sinf(0.5f * tz);
        float cx = cosf(0.5f * tx), sx = sinf(0.5f * tx);
        float* U = g_U[ch][k];
        U[0] = cx * ca;  U[1] = -cx * sa;   // u00 = cx * e^{-ia}
        U[2] = sx * sa;  U[3] = -sx * ca;   // u01 = -i sx * e^{+ia}
        U[4] = -sx * sa; U[5] = -sx * ca;   // u10 = -i sx * e^{-ia}
        U[6] = cx * ca;  U[7] = cx * sa;    // u11 = cx * e^{+ia}
    }
}

// Fused controlled (Rx*Rz) sweep: for ctrl bit set, mix the tgt pair with U.
template <int N, int MC, int MT>
__device__ __forceinline__ void cgate(float (&re)[N], float (&im)[N],
                                      float4 ua, float4 ub) {
#pragma unroll
    for (int i = 0; i < N; i++) {
        if ((i & MC) && !(i & MT)) {
            int j = i | MT;
            float r0 = re[i], m0 = im[i], r1 = re[j], m1 = im[j];
            re[i] = ua.x * r0 - ua.y * m0 + ua.z * r1 - ua.w * m1;
            im[i] = ua.x * m0 + ua.y * r0 + ua.z * m1 + ua.w * r1;
            re[j] = ub.x * r0 - ub.y * m0 + ub.z * r1 - ub.w * m1;
            im[j] = ub.x * m0 + ub.y * r0 + ub.z * m1 + ub.w * r1;
        }
    }
}

// One thread = one (b, h, w, ch) simulation.
// Group A = qubits 0..3 (16 amps, bit j -> qubit 3-j).
// Group B = qubits 4..8 (32 amps, bit j -> qubit 8-j).
// Pairs: k0..2 in A, k3..6 in B, k7=(4,0) folded into the measurement:
//   z = nB0*dA + nB1*dA2.
__global__ void __launch_bounds__(64) quanv_kernel(float* __restrict__ out) {
    int idx = blockIdx.x * 64 + threadIdx.x;
    if (idx >= 28800) return;

    int ch = idx & 3;
    int sp = idx >> 2;
    int w = sp % 30;
    int hb = sp / 30;
    int h = hb % 30;
    int b = hb / 30;

    if (h == 0 || h == 29 || w == 0 || w == 29) {
        out[idx] = 0.0f;
        return;
    }

    // Patch trig (precomputed per pixel): cq = sin(pi p), sq = -cos(pi p)
    float cq[9], sq[9];
    const float2* pb = g_pix + b * 900;
#pragma unroll
    for (int dr = 0; dr < 3; dr++) {
#pragma unroll
        for (int dc = 0; dc < 3; dc++) {
            float2 t = pb[(h - 1 + dr) * 30 + (w - 1 + dc)];
            cq[dr * 3 + dc] = t.x;
            sq[dr * 3 + dc] = t.y;
        }
    }

    const float4* gu = reinterpret_cast<const float4*>(g_U[ch]);

    // ------- Group B init: incremental tensor-product build (32 amps) -------
    float Br[32], Bi[32];
    Br[0] = 1.0f; Bi[0] = 0.0f;
#pragma unroll
    for (int j = 0; j < 5; j++) {
        float c = cq[8 - j], s = sq[8 - j];   // bit j -> qubit 8-j
#pragma unroll
        for (int i = (1 << j) - 1; i >= 0; i--) {
            int hi = i | (1 << j);
            // new amp = old * (-i s) ; old amp *= c
            Br[hi] = s * Bi[i];
            Bi[hi] = -s * Br[i];
            Br[i] *= c;
            Bi[i] *= c;
        }
    }
    // k=3 (8,7): ctrl bit0, tgt bit1
    cgate<32, 1, 2>(Br, Bi, gu[6], gu[7]);
    // k=4 (5,4): ctrl bit3, tgt bit4
    cgate<32, 8, 16>(Br, Bi, gu[8], gu[9]);
    // k=5 (7,6): ctrl bit1, tgt bit2
    cgate<32, 2, 4>(Br, Bi, gu[10], gu[11]);
    // k=6 (6,4): ctrl bit2, tgt bit4
    cgate<32, 4, 16>(Br, Bi, gu[12], gu[13]);

    float nB0 = 0.0f, nB1 = 0.0f;   // qubit4 = bit4
#pragma unroll
    for (int i = 0; i < 32; i++) {
        float p2 = Br[i] * Br[i] + Bi[i] * Bi[i];
        if (i & 16) nB1 += p2; else nB0 += p2;
    }

    // ------- Group A init (16 amps) -------
    float Ar[16], Ai[16];
    Ar[0] = 1.0f; Ai[0] = 0.0f;
#pragma unroll
    for (int j = 0; j < 4; j++) {
        float c = cq[3 - j], s = sq[3 - j];   // bit j -> qubit 3-j
#pragma unroll
        for (int i = (1 << j) - 1; i >= 0; i--) {
            int hi = i | (1 << j);
            Ar[hi] = s * Ai[i];
            Ai[hi] = -s * Ar[i];
            Ar[i] *= c;
            Ai[i] *= c;
        }
    }
    // k=0 (1,0): ctrl bit2, tgt bit3
    cgate<16, 4, 8>(Ar, Ai, gu[0], gu[1]);
    // k=1 (3,2): ctrl bit0, tgt bit1
    cgate<16, 1, 2>(Ar, Ai, gu[2], gu[3]);
    // k=2 (2,0): ctrl bit1, tgt bit3
    cgate<16, 2, 8>(Ar, Ai, gu[4], gu[5]);

    // dA = signed norm over qubit0 (bit3)
    float dA = 0.0f;
#pragma unroll
    for (int i = 0; i < 16; i++) {
        float p2 = Ar[i] * Ar[i] + Ai[i] * Ai[i];
        dA += (i & 8) ? -p2 : p2;
    }

    // dA2: apply fused U (pair k=7) to qubit0 of A, then signed norm.
    float4 ua = gu[14], ub = gu[15];
    float dA2 = 0.0f;
#pragma unroll
    for (int a0 = 0; a0 < 8; a0++) {
        int a1 = a0 | 8;
        float r0 = Ar[a0], m0 = Ai[a0], r1 = Ar[a1], m1 = Ai[a1];
        float n0r = ua.x * r0 - ua.y * m0 + ua.z * r1 - ua.w * m1;
        float n0i = ua.x * m0 + ua.y * r0 + ua.z * m1 + ua.w * r1;
        float n1r = ub.x * r0 - ub.y * m0 + ub.z * r1 - ub.w * m1;
        float n1i = ub.x * m0 + ub.y * r0 + ub.z * m1 + ub.w * r1;
        dA2 += (n0r * n0r + n0i * n0i) - (n1r * n1r + n1i * n1i);
    }

    float z = nB0 * dA + nB1 * dA2;
    out[idx] = 0.5f * (z + 1.0f);
}

extern "C" void kernel_launch(void* const* d_in, const int* in_sizes, int n_in,
                              void* d_out, int out_size) {
    const float* x = (const float*)d_in[0];       // (8,30,30,3) float32
    const float* qp = (const float*)d_in[1];      // (4,16) float32
    float* out = (float*)d_out;                   // (8,30,30,4) float32

    quanv_prep_kernel<<<57, 128>>>(x, qp);        // 7200 pixels + 32 gates
    quanv_kernel<<<450, 64>>>(out);               // 28800 sims, 1 thread each
}

// round 5
// speedup vs baseline: 1.9708x; 1.9708x over previous
#include <cuda_runtime.h>

// Fused controlled (Rx*Rz) sweep: for ctrl bit set, mix the tgt pair with U.
// ua = (u00r,u00i,u01r,u01i), ub = (u10r,u10i,u11r,u11i)
template <int N, int MC, int MT>
__device__ __forceinline__ void cgate(float (&re)[N], float (&im)[N],
                                      float4 ua, float4 ub) {
#pragma unroll
    for (int i = 0; i < N; i++) {
        if ((i & MC) && !(i & MT)) {
            int j = i | MT;
            float r0 = re[i], m0 = im[i], r1 = re[j], m1 = im[j];
            re[i] = ua.x * r0 - ua.y * m0 + ua.z * r1 - ua.w * m1;
            im[i] = ua.x * m0 + ua.y * r0 + ua.z * m1 + ua.w * r1;
            re[j] = ub.x * r0 - ub.y * m0 + ub.z * r1 - ub.w * m1;
            im[j] = ub.x * m0 + ub.y * r0 + ub.z * m1 + ub.w * r1;
        }
    }
}

// Block = 128 threads = 64 sims (16 spatial x 4 channels).
//   warps 0-1: B-group (qubits 4..8, 32 amps) for sims 0..63
//   warps 2-3: A-group (qubits 0..3, 16 amps) for the SAME sims
// Final pair (4,0) + measurement folds to z = nB0*dA + nB1*dA2.
// Amplitude bit convention: group-local bit j -> qubit (top-j).
__global__ void __launch_bounds__(128)
quanv_kernel(const float* __restrict__ x, const float* __restrict__ qp,
             float* __restrict__ out) {
    __shared__ float4 sU[4][16];     // fused gates: [ch][2k], [ch][2k+1]
    __shared__ float2 sTrig[16][9];  // per-spatial patch trig (sin pi p, -cos pi p)
    __shared__ float  sX[4][64];     // nB0, nB1, dA, dA2 per sim

    int tid = threadIdx.x;
    int blk = blockIdx.x;

    // ---- Phase 1a: fused gate table (threads 0..31, one (ch,k) each) ----
    if (tid < 32) {
        int ch = tid >> 3, k = tid & 7;
        float tz = qp[ch * 16 + 2 * k];
        float tx = qp[ch * 16 + 2 * k + 1];
        float sa, ca, sx, cx;
        sincosf(0.5f * tz, &sa, &ca);
        sincosf(0.5f * tx, &sx, &cx);
        // U = Rx(tx)*Rz(tz):
        // u00 = cx e^{-ia}, u01 = -i sx e^{+ia}, u10 = -i sx e^{-ia}, u11 = cx e^{+ia}
        sU[ch][2 * k]     = make_float4(cx * ca, -cx * sa, sx * sa, -sx * ca);
        sU[ch][2 * k + 1] = make_float4(-sx * sa, -sx * ca, cx * ca, cx * sa);
    }

    // ---- Phase 1b: patch-pixel trig, 144 entries over 128 threads ----
    for (int e = tid; e < 144; e += 128) {
        int spl = e / 9, pix = e % 9;
        int spg = blk * 16 + spl;           // global spatial index b*900+h*30+w
        int w = spg % 30;
        int hq = spg / 30;
        int h = hq % 30, b = hq / 30;
        int hp = h - 1 + pix / 3; hp = max(0, min(29, hp));  // clamp: border sims masked later
        int wp = w - 1 + pix % 3; wp = max(0, min(29, wp));
        const float* px = x + ((b * 30 + hp) * 30 + wp) * 3;
        float p = (px[0] + px[1] + px[2]) * (1.0f / 3.0f);
        float s, c;
        sincospif(p, &s, &c);               // RX half-angle: cos=sin(pi p), sin=-cos(pi p)
        sTrig[spl][pix] = make_float2(s, -c);
    }
    __syncthreads();

    // ---- Phase 2: warp-specialized simulation ----
    if (tid < 64) {
        // B-group: qubits 4..8, local bit j -> qubit 8-j -> patch pixel 8-j
        int s = tid;
        int ch = s & 3, spl = s >> 2;
        const float4* gu = sU[ch];
        const float2* tr = sTrig[spl];

        float Br[32], Bi[32];
        Br[0] = 1.0f; Bi[0] = 0.0f;
#pragma unroll
        for (int j = 0; j < 5; j++) {
            float2 t = tr[8 - j];
            float c = t.x, ss = t.y;
#pragma unroll
            for (int i = (1 << j) - 1; i >= 0; i--) {
                int hi = i | (1 << j);
                Br[hi] = ss * Bi[i];
                Bi[hi] = -ss * Br[i];
                Br[i] *= c;
                Bi[i] *= c;
            }
        }
        cgate<32, 1, 2>(Br, Bi, gu[6], gu[7]);     // k=3 (8,7)
        cgate<32, 8, 16>(Br, Bi, gu[8], gu[9]);    // k=4 (5,4)
        cgate<32, 2, 4>(Br, Bi, gu[10], gu[11]);   // k=5 (7,6)
        cgate<32, 4, 16>(Br, Bi, gu[12], gu[13]);  // k=6 (6,4)

        float nB0 = 0.0f, nB1 = 0.0f;              // qubit4 = bit4
#pragma unroll
        for (int i = 0; i < 32; i++) {
            float p2 = Br[i] * Br[i] + Bi[i] * Bi[i];
            if (i & 16) nB1 += p2; else nB0 += p2;
        }
        sX[0][s] = nB0;
        sX[1][s] = nB1;
    } else {
        // A-group: qubits 0..3, local bit j -> qubit 3-j -> patch pixel 3-j
        int s = tid - 64;
        int ch = s & 3, spl = s >> 2;
        const float4* gu = sU[ch];
        const float2* tr = sTrig[spl];

        float Ar[16], Ai[16];
        Ar[0] = 1.0f; Ai[0] = 0.0f;
#pragma unroll
        for (int j = 0; j < 4; j++) {
            float2 t = tr[3 - j];
            float c = t.x, ss = t.y;
#pragma unroll
            for (int i = (1 << j) - 1; i >= 0; i--) {
                int hi = i | (1 << j);
                Ar[hi] = ss * Ai[i];
                Ai[hi] = -ss * Ar[i];
                Ar[i] *= c;
                Ai[i] *= c;
            }
        }
        cgate<16, 4, 8>(Ar, Ai, gu[0], gu[1]);     // k=0 (1,0)
        cgate<16, 1, 2>(Ar, Ai, gu[2], gu[3]);     // k=1 (3,2)
        cgate<16, 2, 8>(Ar, Ai, gu[4], gu[5]);     // k=2 (2,0)

        float dA = 0.0f;                           // signed norm over qubit0 (bit3)
#pragma unroll
        for (int i = 0; i < 16; i++) {
            float p2 = Ar[i] * Ar[i] + Ai[i] * Ai[i];
            dA += (i & 8) ? -p2 : p2;
        }

        float4 ua = gu[14], ub = gu[15];           // final pair k=7 on qubit0
        float dA2 = 0.0f;
#pragma unroll
        for (int a0 = 0; a0 < 8; a0++) {
            int a1 = a0 | 8;
            float r0 = Ar[a0], m0 = Ai[a0], r1 = Ar[a1], m1 = Ai[a1];
            float n0r = ua.x * r0 - ua.y * m0 + ua.z * r1 - ua.w * m1;
            float n0i = ua.x * m0 + ua.y * r0 + ua.z * m1 + ua.w * r1;
            float n1r = ub.x * r0 - ub.y * m0 + ub.z * r1 - ub.w * m1;
            float n1i = ub.x * m0 + ub.y * r0 + ub.z * m1 + ub.w * r1;
            dA2 += (n0r * n0r + n0i * n0i) - (n1r * n1r + n1i * n1i);
        }
        sX[2][s] = dA;
        sX[3][s] = dA2;
    }
    __syncthreads();

    // ---- Phase 3: combine + store (threads 0..63, coalesced 64-float store) ----
    if (tid < 64) {
        int idx = blk * 64 + tid;
        int spg = idx >> 2;
        int w = spg % 30;
        int h = (spg / 30) % 30;
        float v = 0.0f;
        if (h != 0 && h != 29 && w != 0 && w != 29) {
            float z = sX[0][tid] * sX[2][tid] + sX[1][tid] * sX[3][tid];
            v = 0.5f * (z + 1.0f);
        }
        out[idx] = v;
    }
}

extern "C" void kernel_launch(void* const* d_in, const int* in_sizes, int n_in,
                              void* d_out, int out_size) {
    const float* x = (const float*)d_in[0];       // (8,30,30,3) float32
    const float* qp = (const float*)d_in[1];      // (4,16) float32
    float* out = (float*)d_out;                   // (8,30,30,4) float32

    quanv_kernel<<<450, 128>>>(x, qp, out);       // 64 sims per block
}

// round 6
// speedup vs baseline: 2.9013x; 1.4721x over previous
#include <cuda_runtime.h>

// Fused controlled gate sweep in the D-transformed (all-real-init) basis.
// ua = (u00r,u00i,u01r,u01i), ub = (u10r,u10i,u11r,u11i).
// CM: compile-time mask of amplitude indices that are complex on entry.
// Pairs where both members are still real use the half-cost real-input form.
template <int N, int MC, int MT, unsigned CM>
__device__ __forceinline__ void cgate(float (&re)[N], float (&im)[N],
                                      float4 ua, float4 ub) {
#pragma unroll
    for (int i = 0; i < N; i++) {
        if ((i & MC) && !(i & MT)) {
            const int j = i | MT;
            const bool cpx = (((CM >> i) | (CM >> j)) & 1u) != 0u;
            float r0 = re[i], r1 = re[j];
            if (cpx) {
                float m0 = im[i], m1 = im[j];
                re[i] = ua.x * r0 - ua.y * m0 + ua.z * r1 - ua.w * m1;
                im[i] = ua.x * m0 + ua.y * r0 + ua.z * m1 + ua.w * r1;
                re[j] = ub.x * r0 - ub.y * m0 + ub.z * r1 - ub.w * m1;
                im[j] = ub.x * m0 + ub.y * r0 + ub.z * m1 + ub.w * r1;
            } else {
                re[i] = ua.x * r0 + ua.z * r1;
                im[i] = ua.y * r0 + ua.w * r1;
                re[j] = ub.x * r0 + ub.z * r1;
                im[j] = ub.y * r0 + ub.w * r1;
            }
        }
    }
}

// One thread = one (b,h,w,ch) sim, in the basis state' = (⊗q diag(1,i)) state.
// Initial state is REAL: per qubit (cq, sq) with cq=sin(pi p), sq=-cos(pi p).
// Fused pair gate U' = [[cx,-sx],[sx,cx]] * diag(e^{-ia}, e^{+ia}), a=tz/2.
// Group A = qubits 0..3 (16 amps, bit j -> qubit 3-j).
// Group B = qubits 4..8 (32 amps, bit j -> qubit 8-j).
// Final pair (4,0) + measurement: z = nB0*dA + nB1*dA2.
__global__ void __launch_bounds__(128)
quanv_kernel(const float* __restrict__ x, const float* __restrict__ qp,
             float* __restrict__ out) {
    __shared__ float4 sU[4][16];   // [ch][2k]=(u00,u01), [ch][2k+1]=(u10,u11)

    int tid = threadIdx.x;
    if (tid < 32) {
        int ch = tid >> 3, k = tid & 7;
        float tz = qp[ch * 16 + 2 * k];
        float tx = qp[ch * 16 + 2 * k + 1];
        float sa, ca, sx, cx;
        sincosf(0.5f * tz, &sa, &ca);
        sincosf(0.5f * tx, &sx, &cx);
        sU[ch][2 * k]     = make_float4(cx * ca, -cx * sa, -sx * ca, -sx * sa);
        sU[ch][2 * k + 1] = make_float4(sx * ca, -sx * sa,  cx * ca,  cx * sa);
    }
    __syncthreads();

    int idx = blockIdx.x * 128 + tid;          // 225*128 = 28800 exactly
    int ch = idx & 3;
    int sp = idx >> 2;
    int w = sp % 30;
    int hq = sp / 30;
    int h = hq % 30;
    int b = hq / 30;

    if (h == 0 || h == 29 || w == 0 || w == 29) {
        out[idx] = 0.0f;
        return;
    }

    // Patch trig: cq = sin(pi p), sq = -cos(pi p); pixel q = dr*3+dc -> qubit q
    float cq[9], sq[9];
    const float* xb = x + b * 2700;
#pragma unroll
    for (int dr = 0; dr < 3; dr++) {
#pragma unroll
        for (int dc = 0; dc < 3; dc++) {
            const float* px = xb + ((h - 1 + dr) * 30 + (w - 1 + dc)) * 3;
            float p = (px[0] + px[1] + px[2]) * (1.0f / 3.0f);
            float s, c;
            sincospif(p, &s, &c);
            cq[dr * 3 + dc] = s;
            sq[dr * 3 + dc] = -c;
        }
    }

    const float4* gu = sU[ch];

    // ---------------- Group B: 32 amps, real incremental init ----------------
    float Br[32], Bi[32];
#pragma unroll
    for (int i = 0; i < 32; i++) Bi[i] = 0.0f;
    Br[0] = 1.0f;
#pragma unroll
    for (int j = 0; j < 5; j++) {
        float c = cq[8 - j], s = sq[8 - j];    // bit j -> qubit 8-j
#pragma unroll
        for (int i = (1 << j) - 1; i >= 0; i--) {
            Br[i | (1 << j)] = Br[i] * s;
            Br[i] *= c;
        }
    }
    cgate<32, 1, 2,  0x00000000u>(Br, Bi, gu[6], gu[7]);    // k=3 (8,7)
    cgate<32, 8, 16, 0xAAAAAAAAu>(Br, Bi, gu[8], gu[9]);    // k=4 (5,4)
    cgate<32, 2, 4,  0xFFAAFFAAu>(Br, Bi, gu[10], gu[11]);  // k=5 (7,6)
    cgate<32, 4, 16, 0xFFEEFFEEu>(Br, Bi, gu[12], gu[13]);  // k=6 (6,4)

    float nB0 = 0.0f, nB1 = 0.0f;              // qubit4 = bit4; mask 0xFFFEFFFE
#pragma unroll
    for (int i = 0; i < 32; i++) {
        float p2 = Br[i] * Br[i];
        if ((0xFFFEFFFEu >> i) & 1u) p2 += Bi[i] * Bi[i];
        if (i & 16) nB1 += p2; else nB0 += p2;
    }

    // ---------------- Group A: 16 amps ----------------
    float Ar[16], Ai[16];
#pragma unroll
    for (int i = 0; i < 16; i++) Ai[i] = 0.0f;
    Ar[0] = 1.0f;
#pragma unroll
    for (int j = 0; j < 4; j++) {
        float c = cq[3 - j], s = sq[3 - j];    // bit j -> qubit 3-j
#pragma unroll
        for (int i = (1 << j) - 1; i >= 0; i--) {
            Ar[i | (1 << j)] = Ar[i] * s;
            Ar[i] *= c;
        }
    }
    cgate<16, 4, 8, 0x0000u>(Ar, Ai, gu[0], gu[1]);         // k=0 (1,0)
    cgate<16, 1, 2, 0xF0F0u>(Ar, Ai, gu[2], gu[3]);         // k=1 (3,2)
    cgate<16, 2, 8, 0xFAFAu>(Ar, Ai, gu[4], gu[5]);         // k=2 (2,0)

    // dA: signed norm over qubit0 (bit3); real mask 0xFEFE (amps 0, 8 real)
    float dA = 0.0f;
#pragma unroll
    for (int i = 0; i < 16; i++) {
        float p2 = Ar[i] * Ar[i];
        if ((0xFEFEu >> i) & 1u) p2 += Ai[i] * Ai[i];
        dA += (i & 8) ? -p2 : p2;
    }

    // dA2: apply fused U'(k=7) to qubit0 (bit3), signed norm.
    float4 ua = gu[14], ub = gu[15];
    float dA2 = 0.0f;
    {   // pair (0,8): both real
        float r0 = Ar[0], r1 = Ar[8];
        float n0r = ua.x * r0 + ua.z * r1, n0i = ua.y * r0 + ua.w * r1;
        float n1r = ub.x * r0 + ub.z * r1, n1i = ub.y * r0 + ub.w * r1;
        dA2 += (n0r * n0r + n0i * n0i) - (n1r * n1r + n1i * n1i);
    }
#pragma unroll
    for (int a0 = 1; a0 < 8; a0++) {
        int a1 = a0 | 8;
        float r0 = Ar[a0], m0 = Ai[a0], r1 = Ar[a1], m1 = Ai[a1];
        float n0r = ua.x * r0 - ua.y * m0 + ua.z * r1 - ua.w * m1;
        float n0i = ua.x * m0 + ua.y * r0 + ua.z * m1 + ua.w * r1;
        float n1r = ub.x * r0 - ub.y * m0 + ub.z * r1 - ub.w * m1;
        float n1i = ub.x * m0 + ub.y * r0 + ub.z * m1 + ub.w * r1;
        dA2 += (n0r * n0r + n0i * n0i) - (n1r * n1r + n1i * n1i);
    }

    float z = nB0 * dA + nB1 * dA2;
    out[idx] = 0.5f * (z + 1.0f);
}

extern "C" void kernel_launch(void* const* d_in, const int* in_sizes, int n_in,
                              void* d_out, int out_size) {
    const float* x = (const float*)d_in[0];       // (8,30,30,3) float32
    const float* qp = (const float*)d_in[1];      // (4,16) float32
    float* out = (float*)d_out;                   // (8,30,30,4) float32

    quanv_kernel<<<225, 128>>>(x, qp, out);       // single launch, 1 thread/sim
}

// round 9
// speedup vs baseline: 3.2657x; 1.1256x over previous
#include <cuda_runtime.h>

// Apply 2x2 complex gate (rows r0=(u00r,u00i,u01r,u01i), r1=(u10r,u10i,u11r,u11i))
// to a REAL 2-vector (c,s). Result (w0r,w0i,w1r,w1i).
__device__ __forceinline__ float4 mat_real(float4 r0, float4 r1, float c, float s) {
    return make_float4(r0.x * c + r0.z * s, r0.y * c + r0.w * s,
                       r1.x * c + r1.z * s, r1.y * c + r1.w * s);
}
// Same for a complex 2-vector v = (v0r,v0i,v1r,v1i).
__device__ __forceinline__ float4 mat_cpx(float4 r0, float4 r1, float4 v) {
    return make_float4(r0.x * v.x - r0.y * v.y + r0.z * v.z - r0.w * v.w,
                       r0.x * v.y + r0.y * v.x + r0.z * v.w + r0.w * v.z,
                       r1.x * v.x - r1.y * v.y + r1.z * v.z - r1.w * v.w,
                       r1.x * v.y + r1.y * v.x + r1.z * v.w + r1.w * v.z);
}
// <Z> of a 2-vector: |w0|^2 - |w1|^2
__device__ __forceinline__ float dz(float4 v) {
    return v.x * v.x + v.y * v.y - v.z * v.z - v.w * v.w;
}
// |row1 . (c,s)|^2 for real input
__device__ __forceinline__ float p1_real(float4 r1, float c, float s) {
    float tr = r1.x * c + r1.z * s, ti = r1.y * c + r1.w * s;
    return tr * tr + ti * ti;
}

// Classical-branching evaluation (valid because every control is never
// targeted after it controls, and observable Z(q0) + later gates are diagonal
// in all controls). Work in the D=diag(1,i) basis: initial per-qubit vector is
// REAL (c,s) = (sin(pi p), -cos(pi p)); fused pair gate U' = G(tx)*diag(e^-ia, e^ia).
//
// Block = one (b,h) image row: 120 outputs (30 w x 4 ch), 128 threads.
// Phase 1: 90 threads -> pixel trig rows h-1..h+1 (shared by all 4 channels);
//          32 threads -> fused gate table. Phase 2: 1 thread per sim.
__global__ void __launch_bounds__(128)
quanv_kernel(const float* __restrict__ x, const float* __restrict__ qp,
             float* __restrict__ out) {
    __shared__ float4 sU[4][16];   // [ch][2k]=(row0), [ch][2k+1]=(row1)
    __shared__ float2 sT[3][30];   // pixel trig (c,s) for rows h-1,h,h+1

    int tid = threadIdx.x;
    int blk = blockIdx.x;          // = b*30 + h
    int h = blk % 30, b = blk / 30;
    int rowbase = blk * 120;       // output offset of (b,h,0,0)

    if (h == 0 || h == 29) {       // padded border rows: all zeros
        if (tid < 120) out[rowbase + tid] = 0.0f;
        return;
    }

    if (tid < 90) {
        int rr = tid / 30, cc = tid % 30;
        const float* px = x + ((b * 30 + (h - 1 + rr)) * 30 + cc) * 3;
        float p = (px[0] + px[1] + px[2]) * (1.0f / 3.0f);
        float s, c;
        sincospif(p, &s, &c);
        sT[rr][cc] = make_float2(s, -c);
    }
    if (tid >= 96) {               // 32 threads: one (ch,k) each
        int u = tid - 96, ch = u >> 3, k = u & 7;
        float tz = qp[ch * 16 + 2 * k], tx = qp[ch * 16 + 2 * k + 1];
        float sa, ca, sx, cx;
        sincosf(0.5f * tz, &sa, &ca);
        sincosf(0.5f * tx, &sx, &cx);
        sU[ch][2 * k]     = make_float4(cx * ca, -cx * sa, -sx * ca, -sx * sa);
        sU[ch][2 * k + 1] = make_float4(sx * ca, -sx * sa,  cx * ca,  cx * sa);
    }
    __syncthreads();

    if (tid >= 120) return;
    int ch = tid & 3, w = tid >> 2;
    if (w == 0 || w == 29) { out[rowbase + tid] = 0.0f; return; }

    const float4* gu = sU[ch];
    // qubit q = dr*3+dc  ->  sT[dr][w-1+dc]
    float2 q0 = sT[0][w - 1], q1 = sT[0][w], q2 = sT[0][w + 1];
    float2 q3 = sT[1][w - 1], q4 = sT[1][w], q5 = sT[1][w + 1];
    float2 q6 = sT[2][w - 1], q7 = sT[2][w], q8 = sT[2][w + 1];

    // ---------- B side: P(q4 = 1) ----------
    float p8 = q8.y * q8.y;                          // P(q8=1)
    float t7 = p1_real(gu[7], q7.x, q7.y);           // U3 row1 (pair k=3)
    float P7 = (1.0f - p8) * (q7.y * q7.y) + p8 * t7;
    float t6 = p1_real(gu[11], q6.x, q6.y);          // U5 row1 (pair k=5)
    float P6 = (1.0f - P7) * (q6.y * q6.y) + P7 * t6;
    float p5 = q5.y * q5.y;

    // q4 chain: U4 (if q5=1, pair k=4) then U6 (if q6=1, pair k=6)
    float4 m10 = mat_real(gu[8], gu[9], q4.x, q4.y);     // U4 * v4
    float n00 = q4.y * q4.y;
    float n10 = m10.z * m10.z + m10.w * m10.w;
    float n01 = p1_real(gu[13], q4.x, q4.y);             // |row1(U6) v4|^2
    float4 r6 = gu[13];
    float tr = r6.x * m10.x - r6.y * m10.y + r6.z * m10.z - r6.w * m10.w;
    float ti = r6.x * m10.y + r6.y * m10.x + r6.z * m10.w + r6.w * m10.z;
    float n11 = tr * tr + ti * ti;
    float nB1 = (1.0f - p5) * ((1.0f - P6) * n00 + P6 * n01)
              + p5 * ((1.0f - P6) * n10 + P6 * n11);

    // ---------- A side: branch probs for q1, q2 ----------
    float p1p = q1.y * q1.y;
    float p3 = q3.y * q3.y;
    float t2 = p1_real(gu[3], q2.x, q2.y);           // U1 row1 (pair k=1)
    float P2 = (1.0f - p3) * (q2.y * q2.y) + p3 * t2;

    // ---------- q0 chain: U0^{b1} (k=0), U2^{b2} (k=2), U7^{b4} (k=7) ----------
    float4 v10 = mat_real(gu[0], gu[1], q0.x, q0.y);     // U0 * v0
    float4 v01 = mat_real(gu[4], gu[5], q0.x, q0.y);     // U2 * v0
    float4 v11 = mat_cpx(gu[4], gu[5], v10);             // U2 * U0 * v0
    float4 w00 = mat_real(gu[14], gu[15], q0.x, q0.y);   // U7 * v0
    float4 w10 = mat_cpx(gu[14], gu[15], v10);
    float4 w01 = mat_cpx(gu[14], gu[15], v01);
    float4 w11 = mat_cpx(gu[14], gu[15], v11);

    float d00 = q0.x * q0.x - q0.y * q0.y;               // dz of real v0
    float nB0 = 1.0f - nB1;
    float e00 = nB0 * d00 + nB1 * dz(w00);
    float e10 = nB0 * dz(v10) + nB1 * dz(w10);
    float e01 = nB0 * dz(v01) + nB1 * dz(w01);
    float e11 = nB0 * dz(v11) + nB1 * dz(w11);

    float z = (1.0f - p1p) * ((1.0f - P2) * e00 + P2 * e01)
            + p1p * ((1.0f - P2) * e10 + P2 * e11);

    out[rowbase + tid] = 0.5f * (z + 1.0f);
}

extern "C" void kernel_launch(void* const* d_in, const int* in_sizes, int n_in,
                              void* d_out, int out_size) {
    const float* x = (const float*)d_in[0];       // (8,30,30,3) float32
    const float* qp = (const float*)d_in[1];      // (4,16) float32
    float* out = (float*)d_out;                   // (8,30,30,4) float32

    quanv_kernel<<<240, 128>>>(x, qp, out);       // 1 block per image row
}